// round 1
// baseline (speedup 1.0000x reference)
#include <cuda_runtime.h>
#include <math.h>

#define D_MODEL 1024
#define N_HEADS 16
#define HEAD_DIM 64
#define BATCH 4
#define SEQ 2048
#define ROWS (BATCH * SEQ)          // 8192
#define QKV_N (3 * HEAD_DIM)        // 192

// ---------------- scratch (device globals: allocation-free) ----------------
__device__ float g_q[N_HEADS * ROWS * HEAD_DIM];   // [h][b*s][e]
__device__ float g_k[N_HEADS * ROWS * HEAD_DIM];
__device__ float g_v[N_HEADS * ROWS * HEAD_DIM];
__device__ float g_z[ROWS * D_MODEL];              // [b*s][h*64+e]

// ---------------------------------------------------------------------------
// QKV projection: per head h, C[8192,192] = x[8192,1024] @ w_qkv[h][1024,192]
// tile 64x64x16, 16x16 threads, 4x4 microtile.
// ---------------------------------------------------------------------------
__global__ __launch_bounds__(256) void qkv_gemm_kernel(
    const float* __restrict__ x, const float* __restrict__ w_qkv)
{
    const int h  = blockIdx.z;
    const int m0 = blockIdx.y * 64;
    const int n0 = blockIdx.x * 64;
    const float* B = w_qkv + (size_t)h * D_MODEL * QKV_N;

    __shared__ float As[64][16];
    __shared__ float Bs[16][64];

    const int t  = threadIdx.y * 16 + threadIdx.x;
    const int ty = threadIdx.y, tx = threadIdx.x;

    float acc[4][4] = {};

    for (int kb = 0; kb < D_MODEL; kb += 16) {
        #pragma unroll
        for (int l = 0; l < 4; l++) {
            int idx = t + l * 256;          // 0..1023
            int r = idx >> 4, c = idx & 15;
            As[r][c] = x[(size_t)(m0 + r) * D_MODEL + kb + c];
        }
        #pragma unroll
        for (int l = 0; l < 4; l++) {
            int idx = t + l * 256;
            int r = idx >> 6, c = idx & 63;
            Bs[r][c] = B[(size_t)(kb + r) * QKV_N + n0 + c];
        }
        __syncthreads();

        #pragma unroll
        for (int kk = 0; kk < 16; kk++) {
            float a[4], b[4];
            #pragma unroll
            for (int i = 0; i < 4; i++) a[i] = As[ty * 4 + i][kk];
            #pragma unroll
            for (int j = 0; j < 4; j++) b[j] = Bs[kk][tx * 4 + j];
            #pragma unroll
            for (int i = 0; i < 4; i++)
                #pragma unroll
                for (int j = 0; j < 4; j++)
                    acc[i][j] = fmaf(a[i], b[j], acc[i][j]);
        }
        __syncthreads();
    }

    // scatter into Q / K / V  (qkv split along the 192-dim)
    #pragma unroll
    for (int i = 0; i < 4; i++) {
        int row = m0 + ty * 4 + i;
        #pragma unroll
        for (int j = 0; j < 4; j++) {
            int n = n0 + tx * 4 + j;
            float* dst = (n < HEAD_DIM) ? g_q : ((n < 2 * HEAD_DIM) ? g_k : g_v);
            int e = n & (HEAD_DIM - 1);
            dst[((size_t)h * ROWS + row) * HEAD_DIM + e] = acc[i][j];
        }
    }
}

// ---------------------------------------------------------------------------
// Flash-style attention. One CTA = 64 queries of one (b,h); streams K/V in
// 64-row tiles, online softmax, output accumulators in registers.
// dynamic smem layout: Qs[64][65] Ks[64][65] Vs[64][65] Ss[64][65] m/l/a[64]
// ---------------------------------------------------------------------------
#define LDP 65
#define ATTN_SMEM_FLOATS (4 * 64 * LDP + 3 * 64)
#define ATTN_SMEM_BYTES  (ATTN_SMEM_FLOATS * 4)

__global__ __launch_bounds__(256) void attn_kernel()
{
    extern __shared__ float sm[];
    float* Qs   = sm;
    float* Ks   = Qs + 64 * LDP;
    float* Vs   = Ks + 64 * LDP;
    float* Ss   = Vs + 64 * LDP;
    float* mrow = Ss + 64 * LDP;
    float* lrow = mrow + 64;
    float* arow = lrow + 64;

    const int bh = blockIdx.y;           // b*16 + h? -> h = low bits
    const int h  = bh & (N_HEADS - 1);
    const int b  = bh >> 4;
    const int q0 = blockIdx.x * 64;
    const int t  = threadIdx.x;
    const int ty = t >> 4, tx = t & 15;

    const size_t base = ((size_t)h * ROWS + (size_t)b * SEQ) * HEAD_DIM;
    const float* Qg = g_q + base;
    const float* Kg = g_k + base;
    const float* Vg = g_v + base;

    const float scale = 1.0f / (float)HEAD_DIM;   // reference: scale = 1/hd

    // load Q tile (scale folded into Q)
    #pragma unroll
    for (int l = 0; l < 16; l++) {
        int idx = t + l * 256;           // 0..4095
        int r = idx >> 6, c = idx & 63;
        Qs[r * LDP + c] = Qg[(size_t)(q0 + r) * HEAD_DIM + c] * scale;
    }
    if (t < 64) { mrow[t] = -1e30f; lrow[t] = 0.0f; }

    float acc[4][4] = {};

    for (int kt = 0; kt < SEQ; kt += 64) {
        __syncthreads();    // protects Ks/Vs/Ss reuse from previous iter
        #pragma unroll
        for (int l = 0; l < 16; l++) {
            int idx = t + l * 256;
            int r = idx >> 6, c = idx & 63;
            Ks[r * LDP + c] = Kg[(size_t)(kt + r) * HEAD_DIM + c];
            Vs[r * LDP + c] = Vg[(size_t)(kt + r) * HEAD_DIM + c];
        }
        __syncthreads();

        // S = Q K^T (already scaled)
        float s[4][4] = {};
        #pragma unroll 8
        for (int e = 0; e < 64; e++) {
            float qv[4], kv[4];
            #pragma unroll
            for (int i = 0; i < 4; i++) qv[i] = Qs[(ty * 4 + i) * LDP + e];
            #pragma unroll
            for (int j = 0; j < 4; j++) kv[j] = Ks[(tx * 4 + j) * LDP + e];
            #pragma unroll
            for (int i = 0; i < 4; i++)
                #pragma unroll
                for (int j = 0; j < 4; j++)
                    s[i][j] = fmaf(qv[i], kv[j], s[i][j]);
        }
        #pragma unroll
        for (int i = 0; i < 4; i++)
            #pragma unroll
            for (int j = 0; j < 4; j++)
                Ss[(ty * 4 + i) * LDP + tx * 4 + j] = s[i][j];
        __syncthreads();

        // online softmax, one thread per row
        if (t < 64) {
            float m_old = mrow[t];
            float mx = m_old;
            #pragma unroll 8
            for (int j = 0; j < 64; j++) mx = fmaxf(mx, Ss[t * LDP + j]);
            float al = __expf(m_old - mx);
            float sum = 0.0f;
            #pragma unroll 8
            for (int j = 0; j < 64; j++) {
                float p = __expf(Ss[t * LDP + j] - mx);
                Ss[t * LDP + j] = p;
                sum += p;
            }
            lrow[t] = lrow[t] * al + sum;
            mrow[t] = mx;
            arow[t] = al;
        }
        __syncthreads();

        // rescale accumulators, then O += P @ V
        #pragma unroll
        for (int i = 0; i < 4; i++) {
            float al = arow[ty * 4 + i];
            #pragma unroll
            for (int j = 0; j < 4; j++) acc[i][j] *= al;
        }
        #pragma unroll 8
        for (int j = 0; j < 64; j++) {
            float p[4], vv[4];
            #pragma unroll
            for (int i = 0; i < 4; i++) p[i] = Ss[(ty * 4 + i) * LDP + j];
            #pragma unroll
            for (int jj = 0; jj < 4; jj++) vv[jj] = Vs[j * LDP + tx * 4 + jj];
            #pragma unroll
            for (int i = 0; i < 4; i++)
                #pragma unroll
                for (int jj = 0; jj < 4; jj++)
                    acc[i][jj] = fmaf(p[i], vv[jj], acc[i][jj]);
        }
    }
    __syncthreads();

    // write z[b*s][h*64+e], normalized by l
    #pragma unroll
    for (int i = 0; i < 4; i++) {
        int r = ty * 4 + i;
        float inv = 1.0f / lrow[r];
        size_t row = (size_t)b * SEQ + q0 + r;
        #pragma unroll
        for (int jj = 0; jj < 4; jj++) {
            int e = tx * 4 + jj;
            g_z[row * D_MODEL + h * HEAD_DIM + e] = acc[i][jj] * inv;
        }
    }
}

// ---------------------------------------------------------------------------
// Output projection: out[8192,1024] = z[8192,1024] @ w_out[1024,1024]
// ---------------------------------------------------------------------------
__global__ __launch_bounds__(256) void out_gemm_kernel(
    const float* __restrict__ w_out, float* __restrict__ out)
{
    const int m0 = blockIdx.y * 64;
    const int n0 = blockIdx.x * 64;

    __shared__ float As[64][16];
    __shared__ float Bs[16][64];

    const int t  = threadIdx.y * 16 + threadIdx.x;
    const int ty = threadIdx.y, tx = threadIdx.x;

    float acc[4][4] = {};

    for (int kb = 0; kb < D_MODEL; kb += 16) {
        #pragma unroll
        for (int l = 0; l < 4; l++) {
            int idx = t + l * 256;
            int r = idx >> 4, c = idx & 15;
            As[r][c] = g_z[(size_t)(m0 + r) * D_MODEL + kb + c];
        }
        #pragma unroll
        for (int l = 0; l < 4; l++) {
            int idx = t + l * 256;
            int r = idx >> 6, c = idx & 63;
            Bs[r][c] = w_out[(size_t)(kb + r) * D_MODEL + n0 + c];
        }
        __syncthreads();

        #pragma unroll
        for (int kk = 0; kk < 16; kk++) {
            float a[4], bb[4];
            #pragma unroll
            for (int i = 0; i < 4; i++) a[i] = As[ty * 4 + i][kk];
            #pragma unroll
            for (int j = 0; j < 4; j++) bb[j] = Bs[kk][tx * 4 + j];
            #pragma unroll
            for (int i = 0; i < 4; i++)
                #pragma unroll
                for (int j = 0; j < 4; j++)
                    acc[i][j] = fmaf(a[i], bb[j], acc[i][j]);
        }
        __syncthreads();
    }

    #pragma unroll
    for (int i = 0; i < 4; i++) {
        size_t row = m0 + ty * 4 + i;
        #pragma unroll
        for (int j = 0; j < 4; j++)
            out[row * D_MODEL + n0 + tx * 4 + j] = acc[i][j];
    }
}

// ---------------------------------------------------------------------------
extern "C" void kernel_launch(void* const* d_in, const int* in_sizes, int n_in,
                              void* d_out, int out_size)
{
    const float* x     = (const float*)d_in[0];  // [4,2048,1024]
    const float* w_qkv = (const float*)d_in[1];  // [16,1024,192]
    const float* w_out = (const float*)d_in[2];  // [1024,1024]
    float* out = (float*)d_out;                  // [8192,1024]

    cudaFuncSetAttribute(attn_kernel,
                         cudaFuncAttributeMaxDynamicSharedMemorySize,
                         ATTN_SMEM_BYTES);

    dim3 blk(16, 16);
    qkv_gemm_kernel<<<dim3(QKV_N / 64, ROWS / 64, N_HEADS), blk>>>(x, w_qkv);
    attn_kernel<<<dim3(SEQ / 64, BATCH * N_HEADS), 256, ATTN_SMEM_BYTES>>>();
    out_gemm_kernel<<<dim3(D_MODEL / 64, ROWS / 64), blk>>>(w_out, out);
}

// round 2
// speedup vs baseline: 1.3367x; 1.3367x over previous
#include <cuda_runtime.h>
#include <math.h>

#define D_MODEL 1024
#define N_HEADS 16
#define HEAD_DIM 64
#define BATCH 4
#define SEQ 2048
#define ROWS (BATCH * SEQ)          // 8192

// ---------------- scratch (device globals: allocation-free) ----------------
__device__ float g_q[N_HEADS * ROWS * HEAD_DIM];   // [h][b*s][e]
__device__ float g_k[N_HEADS * ROWS * HEAD_DIM];
__device__ float g_v[N_HEADS * ROWS * HEAD_DIM];
__device__ float g_z[ROWS * D_MODEL];              // [b*s][h*64+e]

// ---------------------------------------------------------------------------
// QKV projection. One CTA: C[256,64] = x[256,1024] @ Wchunk[1024,64] for one
// (head, chunk) where chunk selects q/k/v. 256 threads, 16x4 microtile.
// A tile stored k-major (transposed) in smem -> broadcast LDS.128 loads.
// ---------------------------------------------------------------------------
__global__ __launch_bounds__(256, 2) void qkv_kernel(
    const float* __restrict__ x, const float* __restrict__ w_qkv)
{
    const int chunk = blockIdx.x;          // 0=q, 1=k, 2=v
    const int m0    = blockIdx.y * 256;
    const int h     = blockIdx.z;

    __shared__ float As[16][260];          // [k][m], pad 4
    __shared__ float Bs[16][68];           // [k][n], pad 4

    const int t  = threadIdx.x;
    const int tx = t & 15, ty = t >> 4;

    const float* B = w_qkv + (size_t)h * D_MODEL * 192 + chunk * 64;

    float acc[16][4] = {};

    for (int kb = 0; kb < D_MODEL; kb += 16) {
        // A tile 256x16 -> As[k][m]
        {
            const int r  = t >> 2;
            const int kc = (t & 3) * 4;
            #pragma unroll
            for (int u = 0; u < 4; u++) {
                const float4 v = *(const float4*)&x[(size_t)(m0 + r + 64 * u) * D_MODEL + kb + kc];
                As[kc + 0][r + 64 * u] = v.x;
                As[kc + 1][r + 64 * u] = v.y;
                As[kc + 2][r + 64 * u] = v.z;
                As[kc + 3][r + 64 * u] = v.w;
            }
        }
        // B tile 16x64
        {
            const int kr = t >> 4;
            const int nc = (t & 15) * 4;
            *(float4*)&Bs[kr][nc] = *(const float4*)&B[(size_t)(kb + kr) * 192 + nc];
        }
        __syncthreads();

        #pragma unroll
        for (int kk = 0; kk < 16; kk++) {
            float a[16], bb[4];
            #pragma unroll
            for (int g = 0; g < 4; g++) {
                const float4 v = *(const float4*)&As[kk][ty * 4 + 64 * g];
                a[g * 4 + 0] = v.x; a[g * 4 + 1] = v.y;
                a[g * 4 + 2] = v.z; a[g * 4 + 3] = v.w;
            }
            const float4 vb = *(const float4*)&Bs[kk][tx * 4];
            bb[0] = vb.x; bb[1] = vb.y; bb[2] = vb.z; bb[3] = vb.w;
            #pragma unroll
            for (int i = 0; i < 16; i++)
                #pragma unroll
                for (int j = 0; j < 4; j++)
                    acc[i][j] = fmaf(a[i], bb[j], acc[i][j]);
        }
        __syncthreads();
    }

    float* dst = (chunk == 0) ? g_q : ((chunk == 1) ? g_k : g_v);
    #pragma unroll
    for (int g = 0; g < 4; g++)
        #pragma unroll
        for (int i = 0; i < 4; i++) {
            const int row = m0 + ty * 4 + i + 64 * g;
            const float4 o = make_float4(acc[g * 4 + i][0], acc[g * 4 + i][1],
                                         acc[g * 4 + i][2], acc[g * 4 + i][3]);
            *(float4*)&dst[((size_t)h * ROWS + row) * HEAD_DIM + tx * 4] = o;
        }
}

// ---------------------------------------------------------------------------
// Flash attention. CTA = 128 queries of one (b,h); 64-key tiles.
// Q and K stored e-major (transposed) in smem -> conflict-free LDS.128.
// Online softmax fully in registers via shfl_xor over the 16-lane row group.
// ---------------------------------------------------------------------------
#define LQT 132
#define LKT 68
#define LV  68
#define LSS 68
#define ATTN_SMEM_FLOATS (64 * LQT + 64 * LKT + 64 * LV + 128 * LSS)
#define ATTN_SMEM_BYTES  (ATTN_SMEM_FLOATS * 4)

__global__ __launch_bounds__(256, 2) void attn_kernel()
{
    extern __shared__ float sm[];
    float* QT = sm;                   // [64 e][132]  (cols = 128 q rows)
    float* KT = QT + 64 * LQT;        // [64 e][68]   (cols = 64 keys)
    float* Vs = KT + 64 * LKT;        // [64 key][68] (cols = 64 e)
    float* Ss = Vs + 64 * LV;         // [128 q][68]  (cols = 64 keys)

    const int bh = blockIdx.y;
    const int h  = bh & (N_HEADS - 1);
    const int b  = bh >> 4;
    const int q0 = blockIdx.x * 128;
    const int t  = threadIdx.x;
    const int tx = t & 15, ty = t >> 4;

    const size_t base = ((size_t)h * ROWS + (size_t)b * SEQ) * HEAD_DIM;
    const float* Qg = g_q + base;
    const float* Kg = g_k + base;
    const float* Vg = g_v + base;

    const float scale = 1.0f / (float)HEAD_DIM;

    // load Q transposed (scale folded in)
    #pragma unroll
    for (int l = 0; l < 8; l++) {
        const int idx = t + 256 * l;            // 0..2047 float4s
        const int r = idx >> 4;
        const int c = (idx & 15) * 4;
        const float4 v = *(const float4*)&Qg[(size_t)(q0 + r) * HEAD_DIM + c];
        QT[(c + 0) * LQT + r] = v.x * scale;
        QT[(c + 1) * LQT + r] = v.y * scale;
        QT[(c + 2) * LQT + r] = v.z * scale;
        QT[(c + 3) * LQT + r] = v.w * scale;
    }

    float m_[8], l_[8], acc[8][4];
    #pragma unroll
    for (int i = 0; i < 8; i++) {
        m_[i] = -1e30f; l_[i] = 0.0f;
        #pragma unroll
        for (int j = 0; j < 4; j++) acc[i][j] = 0.0f;
    }

    for (int kt = 0; kt < SEQ; kt += 64) {
        __syncthreads();   // K/V/S reuse + (first iter) Q ready
        #pragma unroll
        for (int l = 0; l < 4; l++) {
            const int idx = t + 256 * l;        // 0..1023 float4s
            const int r = idx >> 4;
            const int c = (idx & 15) * 4;
            const float4 kv4 = *(const float4*)&Kg[(size_t)(kt + r) * HEAD_DIM + c];
            KT[(c + 0) * LKT + r] = kv4.x;
            KT[(c + 1) * LKT + r] = kv4.y;
            KT[(c + 2) * LKT + r] = kv4.z;
            KT[(c + 3) * LKT + r] = kv4.w;
            *(float4*)&Vs[r * LV + c] = *(const float4*)&Vg[(size_t)(kt + r) * HEAD_DIM + c];
        }
        __syncthreads();

        // S = Q K^T (scaled): rows ty*8+i, cols tx*4+j
        float s[8][4] = {};
        #pragma unroll 8
        for (int e = 0; e < 64; e++) {
            const float4 qa = *(const float4*)&QT[e * LQT + ty * 8];
            const float4 qb = *(const float4*)&QT[e * LQT + ty * 8 + 4];
            const float4 kv = *(const float4*)&KT[e * LKT + tx * 4];
            const float q[8] = {qa.x, qa.y, qa.z, qa.w, qb.x, qb.y, qb.z, qb.w};
            const float k[4] = {kv.x, kv.y, kv.z, kv.w};
            #pragma unroll
            for (int i = 0; i < 8; i++)
                #pragma unroll
                for (int j = 0; j < 4; j++)
                    s[i][j] = fmaf(q[i], k[j], s[i][j]);
        }

        // register online softmax; row group = 16 lanes sharing ty
        #pragma unroll
        for (int i = 0; i < 8; i++) {
            float mx = fmaxf(fmaxf(s[i][0], s[i][1]), fmaxf(s[i][2], s[i][3]));
            #pragma unroll
            for (int msk = 1; msk < 16; msk <<= 1)
                mx = fmaxf(mx, __shfl_xor_sync(0xffffffffu, mx, msk));
            const float mn = fmaxf(m_[i], mx);
            const float al = __expf(m_[i] - mn);
            float ps = 0.0f;
            #pragma unroll
            for (int j = 0; j < 4; j++) {
                const float p = __expf(s[i][j] - mn);
                s[i][j] = p; ps += p;
            }
            #pragma unroll
            for (int msk = 1; msk < 16; msk <<= 1)
                ps += __shfl_xor_sync(0xffffffffu, ps, msk);
            l_[i] = l_[i] * al + ps;
            m_[i] = mn;
            #pragma unroll
            for (int j = 0; j < 4; j++) acc[i][j] *= al;
            *(float4*)&Ss[(ty * 8 + i) * LSS + tx * 4] =
                make_float4(s[i][0], s[i][1], s[i][2], s[i][3]);
        }
        __syncthreads();

        // O += P @ V : output cols e = tx*4..+3
        #pragma unroll 4
        for (int jb = 0; jb < 16; jb++) {
            float4 vv[4];
            #pragma unroll
            for (int jj = 0; jj < 4; jj++)
                vv[jj] = *(const float4*)&Vs[(jb * 4 + jj) * LV + tx * 4];
            #pragma unroll
            for (int i = 0; i < 8; i++) {
                const float4 p = *(const float4*)&Ss[(ty * 8 + i) * LSS + jb * 4];
                acc[i][0] = fmaf(p.x, vv[0].x, acc[i][0]);
                acc[i][1] = fmaf(p.x, vv[0].y, acc[i][1]);
                acc[i][2] = fmaf(p.x, vv[0].z, acc[i][2]);
                acc[i][3] = fmaf(p.x, vv[0].w, acc[i][3]);
                acc[i][0] = fmaf(p.y, vv[1].x, acc[i][0]);
                acc[i][1] = fmaf(p.y, vv[1].y, acc[i][1]);
                acc[i][2] = fmaf(p.y, vv[1].z, acc[i][2]);
                acc[i][3] = fmaf(p.y, vv[1].w, acc[i][3]);
                acc[i][0] = fmaf(p.z, vv[2].x, acc[i][0]);
                acc[i][1] = fmaf(p.z, vv[2].y, acc[i][1]);
                acc[i][2] = fmaf(p.z, vv[2].z, acc[i][2]);
                acc[i][3] = fmaf(p.z, vv[2].w, acc[i][3]);
                acc[i][0] = fmaf(p.w, vv[3].x, acc[i][0]);
                acc[i][1] = fmaf(p.w, vv[3].y, acc[i][1]);
                acc[i][2] = fmaf(p.w, vv[3].z, acc[i][2]);
                acc[i][3] = fmaf(p.w, vv[3].w, acc[i][3]);
            }
        }
    }

    // normalize + write z
    #pragma unroll
    for (int i = 0; i < 8; i++) {
        const float inv = 1.0f / l_[i];
        const size_t row = (size_t)b * SEQ + q0 + ty * 8 + i;
        const float4 o = make_float4(acc[i][0] * inv, acc[i][1] * inv,
                                     acc[i][2] * inv, acc[i][3] * inv);
        *(float4*)&g_z[row * D_MODEL + h * HEAD_DIM + tx * 4] = o;
    }
}

// ---------------------------------------------------------------------------
// Output projection: out[8192,1024] = z @ w_out. 128x128 tile, 8x8 microtile.
// ---------------------------------------------------------------------------
__global__ __launch_bounds__(256, 2) void out_kernel(
    const float* __restrict__ w_out, float* __restrict__ out)
{
    const int n0 = blockIdx.x * 128;
    const int m0 = blockIdx.y * 128;

    __shared__ float As[16][132];          // [k][m]
    __shared__ float Bs[16][132];          // [k][n]

    const int t  = threadIdx.x;
    const int tx = t & 15, ty = t >> 4;

    float acc[8][8] = {};

    for (int kb = 0; kb < D_MODEL; kb += 16) {
        {
            const int r  = t >> 2;
            const int kc = (t & 3) * 4;
            #pragma unroll
            for (int u = 0; u < 2; u++) {
                const float4 v = *(const float4*)&g_z[(size_t)(m0 + r + 64 * u) * D_MODEL + kb + kc];
                As[kc + 0][r + 64 * u] = v.x;
                As[kc + 1][r + 64 * u] = v.y;
                As[kc + 2][r + 64 * u] = v.z;
                As[kc + 3][r + 64 * u] = v.w;
            }
        }
        {
            const int kr = t >> 4;
            const int nc = (t & 15) * 4;
            #pragma unroll
            for (int u = 0; u < 2; u++)
                *(float4*)&Bs[kr][nc + 64 * u] =
                    *(const float4*)&w_out[(size_t)(kb + kr) * D_MODEL + n0 + nc + 64 * u];
        }
        __syncthreads();

        #pragma unroll
        for (int kk = 0; kk < 16; kk++) {
            float a[8], bb[8];
            const float4 a0 = *(const float4*)&As[kk][ty * 4];
            const float4 a1 = *(const float4*)&As[kk][ty * 4 + 64];
            a[0] = a0.x; a[1] = a0.y; a[2] = a0.z; a[3] = a0.w;
            a[4] = a1.x; a[5] = a1.y; a[6] = a1.z; a[7] = a1.w;
            const float4 b0 = *(const float4*)&Bs[kk][tx * 4];
            const float4 b1 = *(const float4*)&Bs[kk][tx * 4 + 64];
            bb[0] = b0.x; bb[1] = b0.y; bb[2] = b0.z; bb[3] = b0.w;
            bb[4] = b1.x; bb[5] = b1.y; bb[6] = b1.z; bb[7] = b1.w;
            #pragma unroll
            for (int i = 0; i < 8; i++)
                #pragma unroll
                for (int j = 0; j < 8; j++)
                    acc[i][j] = fmaf(a[i], bb[j], acc[i][j]);
        }
        __syncthreads();
    }

    #pragma unroll
    for (int rh = 0; rh < 2; rh++)
        #pragma unroll
        for (int i = 0; i < 4; i++) {
            const size_t row = m0 + ty * 4 + i + 64 * rh;
            #pragma unroll
            for (int ch = 0; ch < 2; ch++) {
                const float4 o = make_float4(acc[rh * 4 + i][ch * 4 + 0],
                                             acc[rh * 4 + i][ch * 4 + 1],
                                             acc[rh * 4 + i][ch * 4 + 2],
                                             acc[rh * 4 + i][ch * 4 + 3]);
                *(float4*)&out[row * D_MODEL + n0 + tx * 4 + 64 * ch] = o;
            }
        }
}

// ---------------------------------------------------------------------------
extern "C" void kernel_launch(void* const* d_in, const int* in_sizes, int n_in,
                              void* d_out, int out_size)
{
    const float* x     = (const float*)d_in[0];  // [4,2048,1024]
    const float* w_qkv = (const float*)d_in[1];  // [16,1024,192]
    const float* w_out = (const float*)d_in[2];  // [1024,1024]
    float* out = (float*)d_out;                  // [8192,1024]

    cudaFuncSetAttribute(attn_kernel,
                         cudaFuncAttributeMaxDynamicSharedMemorySize,
                         ATTN_SMEM_BYTES);

    qkv_kernel<<<dim3(3, ROWS / 256, N_HEADS), 256>>>(x, w_qkv);
    attn_kernel<<<dim3(SEQ / 128, BATCH * N_HEADS), 256, ATTN_SMEM_BYTES>>>();
    out_kernel<<<dim3(D_MODEL / 128, ROWS / 128), 256>>>(w_out, out);
}

// round 11
// speedup vs baseline: 1.8569x; 1.3892x over previous
#include <cuda_runtime.h>
#include <cuda_bf16.h>
#include <stdint.h>
#include <math.h>

#define D_MODEL 1024
#define N_HEADS 16
#define HEAD_DIM 64
#define BATCH 4
#define SEQ 2048
#define ROWS (BATCH * SEQ)          // 8192
#define NQKV 3072                   // 16 heads * 192

// ---------------- scratch (device globals: allocation-free) ----------------
__device__ float g_qkv[(size_t)ROWS * NQKV];     // [row][h*192 + {q|k|v}*64 + e]
__device__ float g_z[(size_t)ROWS * D_MODEL];    // [row][h*64+e]
__device__ __nv_bfloat16 gBq_hi[(size_t)NQKV * D_MODEL];   // [n][k] K-major
__device__ __nv_bfloat16 gBq_lo[(size_t)NQKV * D_MODEL];
__device__ __nv_bfloat16 gBo_hi[(size_t)D_MODEL * D_MODEL];
__device__ __nv_bfloat16 gBo_lo[(size_t)D_MODEL * D_MODEL];

// ======================= helpers =============================
static __device__ __forceinline__ uint32_t smem_u32(const void* p) {
    uint32_t a;
    asm("{ .reg .u64 t; cvta.to.shared.u64 t, %1; cvt.u32.u64 %0, t; }"
        : "=r"(a) : "l"(p));
    return a;
}
static __device__ __forceinline__ void ldsm4(uint32_t* r, uint32_t addr) {
    asm volatile("ldmatrix.sync.aligned.m8n8.x4.shared.b16 {%0,%1,%2,%3}, [%4];"
                 : "=r"(r[0]), "=r"(r[1]), "=r"(r[2]), "=r"(r[3]) : "r"(addr));
}
static __device__ __forceinline__ void mma16816(float* d, const uint32_t* a,
                                                uint32_t b0, uint32_t b1) {
    asm volatile(
        "mma.sync.aligned.m16n8k16.row.col.f32.bf16.bf16.f32 "
        "{%0,%1,%2,%3}, {%4,%5,%6,%7}, {%8,%9}, {%0,%1,%2,%3};"
        : "+f"(d[0]), "+f"(d[1]), "+f"(d[2]), "+f"(d[3])
        : "r"(a[0]), "r"(a[1]), "r"(a[2]), "r"(a[3]), "r"(b0), "r"(b1));
}

// ===========================================================================
// Weight reformat: -> [n][k] K-major hi/lo bf16
// ===========================================================================
__global__ __launch_bounds__(256) void fmt_wqkv_kernel(const float* __restrict__ w)
{
    const int n = blockIdx.x;
    const int h = n / 192, e = n - h * 192;
    const float* src = w + (size_t)h * D_MODEL * 192 + e;
    for (int k = threadIdx.x; k < D_MODEL; k += 256) {
        const float v = src[(size_t)k * 192];
        const __nv_bfloat16 hi = __float2bfloat16(v);
        const __nv_bfloat16 lo = __float2bfloat16(v - __bfloat162float(hi));
        gBq_hi[(size_t)n * D_MODEL + k] = hi;
        gBq_lo[(size_t)n * D_MODEL + k] = lo;
    }
}
__global__ __launch_bounds__(256) void fmt_wout_kernel(const float* __restrict__ w)
{
    const int n = blockIdx.x;
    for (int k = threadIdx.x; k < D_MODEL; k += 256) {
        const float v = w[(size_t)k * D_MODEL + n];
        const __nv_bfloat16 hi = __float2bfloat16(v);
        const __nv_bfloat16 lo = __float2bfloat16(v - __bfloat162float(hi));
        gBo_hi[(size_t)n * D_MODEL + k] = hi;
        gBo_lo[(size_t)n * D_MODEL + k] = lo;
    }
}

// ===========================================================================
// bf16-split HMMA GEMM: C[M,Ntot] = A[M,1024](fp32) @ B[Ntot,1024]^T
// CTA 128x128, K-tile 32, 8 warps (2m x 4n), warp tile 64x32 (4x4 m16n8k16).
// smem rows padded to 40 bf16 (80B) -> conflict-free ldmatrix.
// ===========================================================================
#define LDR 40              // bf16 per smem row (80 bytes)
#define TILE_BYTES (128 * LDR * 2)          // 10240 per split
#define SOFF_AHI 0
#define SOFF_ALO (TILE_BYTES)
#define SOFF_BHI (2 * TILE_BYTES)
#define SOFF_BLO (3 * TILE_BYTES)

__global__ __launch_bounds__(256, 2) void gemm_kernel(
    const float* __restrict__ A,
    const __nv_bfloat16* __restrict__ Bhi,
    const __nv_bfloat16* __restrict__ Blo,
    float* __restrict__ C, int Ntot)
{
    __shared__ __align__(16) char smx[4 * TILE_BYTES];   // 40 KB static
    const uint32_t sbase = smem_u32(smx);

    const int t = threadIdx.x;
    const int lane = t & 31, wid = t >> 5;
    const int warp_m = wid >> 2;        // 0..1 (64 rows each)
    const int warp_n = wid & 3;         // 0..3 (32 cols each)
    const int n0 = blockIdx.x * 128, m0 = blockIdx.y * 128;

    // per-lane ldmatrix offsets (bytes)
    const uint32_t aoff = (uint32_t)(((lane & 7) + ((lane >> 3) & 1) * 8) * (LDR * 2)
                                     + ((lane >> 4) & 1) * 16);
    const uint32_t boff = (uint32_t)(((lane & 7) + ((lane >> 4) & 1) * 8) * (LDR * 2)
                                     + ((lane >> 3) & 1) * 16);

    float acc[4][4][4];
    #pragma unroll
    for (int i = 0; i < 4; i++)
        #pragma unroll
        for (int j = 0; j < 4; j++)
            #pragma unroll
            for (int v = 0; v < 4; v++) acc[i][j][v] = 0.0f;

    for (int kb = 0; kb < D_MODEL; kb += 32) {
        __syncthreads();
        // ---- fill A hi/lo: 128 rows x 32 fp32 -> bf16 split ----
        #pragma unroll
        for (int u = 0; u < 4; u++) {
            const int idx = t + 256 * u;        // 0..1023 float4s
            const int r = idx >> 3;
            const int c4 = (idx & 7) * 4;
            const float4 v = *(const float4*)&A[(size_t)(m0 + r) * D_MODEL + kb + c4];
            const __nv_bfloat16 h0 = __float2bfloat16(v.x);
            const __nv_bfloat16 h1 = __float2bfloat16(v.y);
            const __nv_bfloat16 h2 = __float2bfloat16(v.z);
            const __nv_bfloat16 h3 = __float2bfloat16(v.w);
            const __nv_bfloat16 l0 = __float2bfloat16(v.x - __bfloat162float(h0));
            const __nv_bfloat16 l1 = __float2bfloat16(v.y - __bfloat162float(h1));
            const __nv_bfloat16 l2 = __float2bfloat16(v.z - __bfloat162float(h2));
            const __nv_bfloat16 l3 = __float2bfloat16(v.w - __bfloat162float(h3));
            __nv_bfloat162 H0(h0, h1), H1(h2, h3), L0(l0, l1), L1(l2, l3);
            uint2 uh, ul;
            uh.x = *(uint32_t*)&H0; uh.y = *(uint32_t*)&H1;
            ul.x = *(uint32_t*)&L0; ul.y = *(uint32_t*)&L1;
            const uint32_t so = (uint32_t)(r * (LDR * 2) + c4 * 2);
            *(uint2*)(smx + SOFF_AHI + so) = uh;
            *(uint2*)(smx + SOFF_ALO + so) = ul;
        }
        // ---- fill B hi/lo: 128 n-rows x 32 bf16 (K-major gmem) ----
        #pragma unroll
        for (int u = 0; u < 2; u++) {
            const int idx = t + 256 * u;        // 0..511 uint4s
            const int r = idx >> 2;
            const int q = idx & 3;
            const size_t e = (size_t)(n0 + r) * D_MODEL + kb + q * 8;
            const uint32_t so = (uint32_t)(r * (LDR * 2) + q * 16);
            *(uint4*)(smx + SOFF_BHI + so) = *(const uint4*)&Bhi[e];
            *(uint4*)(smx + SOFF_BLO + so) = *(const uint4*)&Blo[e];
        }
        __syncthreads();

        #pragma unroll
        for (int ks = 0; ks < 2; ks++) {
            const uint32_t kbyte = (uint32_t)(ks * 32);
            // B fragments: two x4 loads per split cover 4 n-tiles
            uint32_t bh[8], bl[8];
            #pragma unroll
            for (int g = 0; g < 2; g++) {
                const uint32_t nbase = (uint32_t)((warp_n * 32 + g * 16) * (LDR * 2));
                ldsm4(&bh[g * 4], sbase + SOFF_BHI + nbase + kbyte + boff);
                ldsm4(&bl[g * 4], sbase + SOFF_BLO + nbase + kbyte + boff);
            }
            #pragma unroll
            for (int mt = 0; mt < 4; mt++) {
                const uint32_t mbase = (uint32_t)((warp_m * 64 + mt * 16) * (LDR * 2));
                uint32_t ah[4], al[4];
                ldsm4(ah, sbase + SOFF_AHI + mbase + kbyte + aoff);
                ldsm4(al, sbase + SOFF_ALO + mbase + kbyte + aoff);
                #pragma unroll
                for (int nt = 0; nt < 4; nt++) {
                    const int g = nt >> 1, j = (nt & 1) * 2;
                    mma16816(acc[mt][nt], ah, bh[g * 4 + j], bh[g * 4 + j + 1]);
                    mma16816(acc[mt][nt], ah, bl[g * 4 + j], bl[g * 4 + j + 1]);
                    mma16816(acc[mt][nt], al, bh[g * 4 + j], bh[g * 4 + j + 1]);
                }
            }
        }
    }

    // ---- epilogue: write C ----
    #pragma unroll
    for (int mt = 0; mt < 4; mt++) {
        const int row = m0 + warp_m * 64 + mt * 16 + (lane >> 2);
        #pragma unroll
        for (int nt = 0; nt < 4; nt++) {
            const int col = n0 + warp_n * 32 + nt * 8 + (lane & 3) * 2;
            float2 v0 = make_float2(acc[mt][nt][0], acc[mt][nt][1]);
            float2 v1 = make_float2(acc[mt][nt][2], acc[mt][nt][3]);
            *(float2*)&C[(size_t)row * Ntot + col] = v0;
            *(float2*)&C[(size_t)(row + 8) * Ntot + col] = v1;
        }
    }
}

// ===========================================================================
// Flash attention (fp32 SIMT, unchanged math). Reads fused g_qkv.
// ===========================================================================
#define LQT 132
#define LKT 68
#define LV  68
#define LSS 68
#define ATTN_SMEM_FLOATS (64 * LQT + 64 * LKT + 64 * LV + 128 * LSS)
#define ATTN_SMEM_BYTES  (ATTN_SMEM_FLOATS * 4)

__global__ __launch_bounds__(256, 2) void attn_kernel()
{
    extern __shared__ float smf[];
    float* QT = smf;                  // [64 e][132]
    float* KT = QT + 64 * LQT;        // [64 e][68]
    float* Vs = KT + 64 * LKT;        // [64 key][68]
    float* Ss = Vs + 64 * LV;         // [128 q][68]

    const int bh = blockIdx.y;
    const int h  = bh & (N_HEADS - 1);
    const int b  = bh >> 4;
    const int q0 = blockIdx.x * 128;
    const int t  = threadIdx.x;
    const int tx = t & 15, ty = t >> 4;

    const float* Bg = g_qkv + (size_t)b * SEQ * NQKV + h * 192;
    const float scale = 1.0f / (float)HEAD_DIM;

    #pragma unroll
    for (int l = 0; l < 8; l++) {
        const int idx = t + 256 * l;
        const int r = idx >> 4;
        const int c = (idx & 15) * 4;
        const float4 v = *(const float4*)&Bg[(size_t)(q0 + r) * NQKV + c];
        QT[(c + 0) * LQT + r] = v.x * scale;
        QT[(c + 1) * LQT + r] = v.y * scale;
        QT[(c + 2) * LQT + r] = v.z * scale;
        QT[(c + 3) * LQT + r] = v.w * scale;
    }

    float m_[8], l_[8], acc[8][4];
    #pragma unroll
    for (int i = 0; i < 8; i++) {
        m_[i] = -1e30f; l_[i] = 0.0f;
        #pragma unroll
        for (int j = 0; j < 4; j++) acc[i][j] = 0.0f;
    }

    for (int kt = 0; kt < SEQ; kt += 64) {
        __syncthreads();
        #pragma unroll
        for (int l = 0; l < 4; l++) {
            const int idx = t + 256 * l;
            const int r = idx >> 4;
            const int c = (idx & 15) * 4;
            const float4 kv4 = *(const float4*)&Bg[(size_t)(kt + r) * NQKV + 64 + c];
            KT[(c + 0) * LKT + r] = kv4.x;
            KT[(c + 1) * LKT + r] = kv4.y;
            KT[(c + 2) * LKT + r] = kv4.z;
            KT[(c + 3) * LKT + r] = kv4.w;
            *(float4*)&Vs[r * LV + c] =
                *(const float4*)&Bg[(size_t)(kt + r) * NQKV + 128 + c];
        }
        __syncthreads();

        float s[8][4] = {};
        #pragma unroll 8
        for (int e = 0; e < 64; e++) {
            const float4 qa = *(const float4*)&QT[e * LQT + ty * 8];
            const float4 qb = *(const float4*)&QT[e * LQT + ty * 8 + 4];
            const float4 kv = *(const float4*)&KT[e * LKT + tx * 4];
            const float q[8] = {qa.x, qa.y, qa.z, qa.w, qb.x, qb.y, qb.z, qb.w};
            const float k[4] = {kv.x, kv.y, kv.z, kv.w};
            #pragma unroll
            for (int i = 0; i < 8; i++)
                #pragma unroll
                for (int j = 0; j < 4; j++)
                    s[i][j] = fmaf(q[i], k[j], s[i][j]);
        }

        #pragma unroll
        for (int i = 0; i < 8; i++) {
            float mx = fmaxf(fmaxf(s[i][0], s[i][1]), fmaxf(s[i][2], s[i][3]));
            #pragma unroll
            for (int msk = 1; msk < 16; msk <<= 1)
                mx = fmaxf(mx, __shfl_xor_sync(0xffffffffu, mx, msk));
            const float mn = fmaxf(m_[i], mx);
            const float al = __expf(m_[i] - mn);
            float ps = 0.0f;
            #pragma unroll
            for (int j = 0; j < 4; j++) {
                const float p = __expf(s[i][j] - mn);
                s[i][j] = p; ps += p;
            }
            #pragma unroll
            for (int msk = 1; msk < 16; msk <<= 1)
                ps += __shfl_xor_sync(0xffffffffu, ps, msk);
            l_[i] = l_[i] * al + ps;
            m_[i] = mn;
            #pragma unroll
            for (int j = 0; j < 4; j++) acc[i][j] *= al;
            *(float4*)&Ss[(ty * 8 + i) * LSS + tx * 4] =
                make_float4(s[i][0], s[i][1], s[i][2], s[i][3]);
        }
        __syncthreads();

        #pragma unroll 4
        for (int jb = 0; jb < 16; jb++) {
            float4 vv[4];
            #pragma unroll
            for (int jj = 0; jj < 4; jj++)
                vv[jj] = *(const float4*)&Vs[(jb * 4 + jj) * LV + tx * 4];
            #pragma unroll
            for (int i = 0; i < 8; i++) {
                const float4 p = *(const float4*)&Ss[(ty * 8 + i) * LSS + jb * 4];
                acc[i][0] = fmaf(p.x, vv[0].x, acc[i][0]);
                acc[i][1] = fmaf(p.x, vv[0].y, acc[i][1]);
                acc[i][2] = fmaf(p.x, vv[0].z, acc[i][2]);
                acc[i][3] = fmaf(p.x, vv[0].w, acc[i][3]);
                acc[i][0] = fmaf(p.y, vv[1].x, acc[i][0]);
                acc[i][1] = fmaf(p.y, vv[1].y, acc[i][1]);
                acc[i][2] = fmaf(p.y, vv[1].z, acc[i][2]);
                acc[i][3] = fmaf(p.y, vv[1].w, acc[i][3]);
                acc[i][0] = fmaf(p.z, vv[2].x, acc[i][0]);
                acc[i][1] = fmaf(p.z, vv[2].y, acc[i][1]);
                acc[i][2] = fmaf(p.z, vv[2].z, acc[i][2]);
                acc[i][3] = fmaf(p.z, vv[2].w, acc[i][3]);
                acc[i][0] = fmaf(p.w, vv[3].x, acc[i][0]);
                acc[i][1] = fmaf(p.w, vv[3].y, acc[i][1]);
                acc[i][2] = fmaf(p.w, vv[3].z, acc[i][2]);
                acc[i][3] = fmaf(p.w, vv[3].w, acc[i][3]);
            }
        }
    }

    #pragma unroll
    for (int i = 0; i < 8; i++) {
        const float inv = 1.0f / l_[i];
        const size_t row = (size_t)b * SEQ + q0 + ty * 8 + i;
        const float4 o = make_float4(acc[i][0] * inv, acc[i][1] * inv,
                                     acc[i][2] * inv, acc[i][3] * inv);
        *(float4*)&g_z[row * D_MODEL + h * HEAD_DIM + tx * 4] = o;
    }
}

// ===========================================================================
extern "C" void kernel_launch(void* const* d_in, const int* in_sizes, int n_in,
                              void* d_out, int out_size)
{
    const float* x     = (const float*)d_in[0];  // [4,2048,1024]
    const float* w_qkv = (const float*)d_in[1];  // [16,1024,192]
    const float* w_out = (const float*)d_in[2];  // [1024,1024]
    float* out = (float*)d_out;                  // [8192,1024]

    cudaFuncSetAttribute(attn_kernel,
                         cudaFuncAttributeMaxDynamicSharedMemorySize,
                         ATTN_SMEM_BYTES);

    fmt_wqkv_kernel<<<NQKV, 256>>>(w_qkv);
    fmt_wout_kernel<<<D_MODEL, 256>>>(w_out);

    __nv_bfloat16 *bqh, *bql, *boh, *bol;
    float *qkvp, *zp;
    cudaGetSymbolAddress((void**)&bqh, gBq_hi);
    cudaGetSymbolAddress((void**)&bql, gBq_lo);
    cudaGetSymbolAddress((void**)&boh, gBo_hi);
    cudaGetSymbolAddress((void**)&bol, gBo_lo);
    cudaGetSymbolAddress((void**)&qkvp, g_qkv);
    cudaGetSymbolAddress((void**)&zp, g_z);

    gemm_kernel<<<dim3(NQKV / 128, ROWS / 128), 256>>>(x, bqh, bql, qkvp, NQKV);
    attn_kernel<<<dim3(SEQ / 128, BATCH * N_HEADS), 256, ATTN_SMEM_BYTES>>>();
    gemm_kernel<<<dim3(D_MODEL / 128, ROWS / 128), 256>>>(zp, boh, bol, out, D_MODEL);
}

// round 13
// speedup vs baseline: 4.3825x; 2.3601x over previous
#include <cuda_runtime.h>
#include <cuda_bf16.h>
#include <cuda_fp16.h>
#include <stdint.h>
#include <math.h>

#define D_MODEL 1024
#define N_HEADS 16
#define HEAD_DIM 64
#define BATCH 4
#define SEQ 2048
#define ROWS (BATCH * SEQ)          // 8192
#define NQKV 3072                   // 16 heads * 192

// ---------------- scratch (device globals: allocation-free) ----------------
__device__ float g_qkv[(size_t)ROWS * NQKV];     // fp32 from qkv gemm
__device__ __half g_qkvh[(size_t)ROWS * NQKV];   // fp16, Q section pre-scaled
__device__ float g_z[(size_t)ROWS * D_MODEL];    // attn out [row][h*64+e]
__device__ __nv_bfloat16 gBq_hi[(size_t)NQKV * D_MODEL];   // [n][k] K-major
__device__ __nv_bfloat16 gBq_lo[(size_t)NQKV * D_MODEL];
__device__ __nv_bfloat16 gBo_hi[(size_t)D_MODEL * D_MODEL];
__device__ __nv_bfloat16 gBo_lo[(size_t)D_MODEL * D_MODEL];

// ======================= helpers =============================
static __device__ __forceinline__ uint32_t smem_u32(const void* p) {
    uint32_t a;
    asm("{ .reg .u64 t; cvta.to.shared.u64 t, %1; cvt.u32.u64 %0, t; }"
        : "=r"(a) : "l"(p));
    return a;
}
static __device__ __forceinline__ void ldsm4(uint32_t* r, uint32_t addr) {
    asm volatile("ldmatrix.sync.aligned.m8n8.x4.shared.b16 {%0,%1,%2,%3}, [%4];"
                 : "=r"(r[0]), "=r"(r[1]), "=r"(r[2]), "=r"(r[3]) : "r"(addr));
}
static __device__ __forceinline__ void ldsm4t(uint32_t* r, uint32_t addr) {
    asm volatile("ldmatrix.sync.aligned.m8n8.x4.trans.shared.b16 {%0,%1,%2,%3}, [%4];"
                 : "=r"(r[0]), "=r"(r[1]), "=r"(r[2]), "=r"(r[3]) : "r"(addr));
}
static __device__ __forceinline__ void mma16816(float* d, const uint32_t* a,
                                                uint32_t b0, uint32_t b1) {
    asm volatile(
        "mma.sync.aligned.m16n8k16.row.col.f32.bf16.bf16.f32 "
        "{%0,%1,%2,%3}, {%4,%5,%6,%7}, {%8,%9}, {%0,%1,%2,%3};"
        : "+f"(d[0]), "+f"(d[1]), "+f"(d[2]), "+f"(d[3])
        : "r"(a[0]), "r"(a[1]), "r"(a[2]), "r"(a[3]), "r"(b0), "r"(b1));
}
static __device__ __forceinline__ void mma16816h(float* d, const uint32_t* a,
                                                 uint32_t b0, uint32_t b1) {
    asm volatile(
        "mma.sync.aligned.m16n8k16.row.col.f32.f16.f16.f32 "
        "{%0,%1,%2,%3}, {%4,%5,%6,%7}, {%8,%9}, {%0,%1,%2,%3};"
        : "+f"(d[0]), "+f"(d[1]), "+f"(d[2]), "+f"(d[3])
        : "r"(a[0]), "r"(a[1]), "r"(a[2]), "r"(a[3]), "r"(b0), "r"(b1));
}

// ===========================================================================
// Weight reformat: -> [n][k] K-major hi/lo bf16
// ===========================================================================
__global__ __launch_bounds__(256) void fmt_wqkv_kernel(const float* __restrict__ w)
{
    const int n = blockIdx.x;
    const int h = n / 192, e = n - h * 192;
    const float* src = w + (size_t)h * D_MODEL * 192 + e;
    for (int k = threadIdx.x; k < D_MODEL; k += 256) {
        const float v = src[(size_t)k * 192];
        const __nv_bfloat16 hi = __float2bfloat16(v);
        const __nv_bfloat16 lo = __float2bfloat16(v - __bfloat162float(hi));
        gBq_hi[(size_t)n * D_MODEL + k] = hi;
        gBq_lo[(size_t)n * D_MODEL + k] = lo;
    }
}
__global__ __launch_bounds__(256) void fmt_wout_kernel(const float* __restrict__ w)
{
    const int n = blockIdx.x;
    for (int k = threadIdx.x; k < D_MODEL; k += 256) {
        const float v = w[(size_t)k * D_MODEL + n];
        const __nv_bfloat16 hi = __float2bfloat16(v);
        const __nv_bfloat16 lo = __float2bfloat16(v - __bfloat162float(hi));
        gBo_hi[(size_t)n * D_MODEL + k] = hi;
        gBo_lo[(size_t)n * D_MODEL + k] = lo;
    }
}

// qkv fp32 -> fp16, scaling the q section by 1/64 (softmax scale folded in)
__global__ __launch_bounds__(256) void fmt_qkvh_kernel()
{
    const size_t row = blockIdx.x;
    const float* src = g_qkv + row * NQKV;
    __half* dst = g_qkvh + row * NQKV;
    for (int n4 = threadIdx.x * 4; n4 < NQKV; n4 += 256 * 4) {
        const float4 v = *(const float4*)&src[n4];
        const int sec = (n4 % 192) / 64;           // 0=q,1=k,2=v (const over 4)
        const float sc = (sec == 0) ? (1.0f / 64.0f) : 1.0f;
        __half2 h0 = __floats2half2_rn(v.x * sc, v.y * sc);
        __half2 h1 = __floats2half2_rn(v.z * sc, v.w * sc);
        uint2 u; u.x = *(uint32_t*)&h0; u.y = *(uint32_t*)&h1;
        *(uint2*)&dst[n4] = u;
    }
}

// ===========================================================================
// bf16-split HMMA GEMM (unchanged, validated R11): C = A @ B^T
// ===========================================================================
#define LDR 40              // bf16 per smem row (80 bytes)
#define TILE_BYTES (128 * LDR * 2)
#define SOFF_AHI 0
#define SOFF_ALO (TILE_BYTES)
#define SOFF_BHI (2 * TILE_BYTES)
#define SOFF_BLO (3 * TILE_BYTES)

__global__ __launch_bounds__(256, 2) void gemm_kernel(
    const float* __restrict__ A,
    const __nv_bfloat16* __restrict__ Bhi,
    const __nv_bfloat16* __restrict__ Blo,
    float* __restrict__ C, int Ntot)
{
    __shared__ __align__(16) char smx[4 * TILE_BYTES];
    const uint32_t sbase = smem_u32(smx);

    const int t = threadIdx.x;
    const int lane = t & 31, wid = t >> 5;
    const int warp_m = wid >> 2;
    const int warp_n = wid & 3;
    const int n0 = blockIdx.x * 128, m0 = blockIdx.y * 128;

    const uint32_t aoff = (uint32_t)(((lane & 7) + ((lane >> 3) & 1) * 8) * (LDR * 2)
                                     + ((lane >> 4) & 1) * 16);
    const uint32_t boff = (uint32_t)(((lane & 7) + ((lane >> 4) & 1) * 8) * (LDR * 2)
                                     + ((lane >> 3) & 1) * 16);

    float acc[4][4][4];
    #pragma unroll
    for (int i = 0; i < 4; i++)
        #pragma unroll
        for (int j = 0; j < 4; j++)
            #pragma unroll
            for (int v = 0; v < 4; v++) acc[i][j][v] = 0.0f;

    for (int kb = 0; kb < D_MODEL; kb += 32) {
        __syncthreads();
        #pragma unroll
        for (int u = 0; u < 4; u++) {
            const int idx = t + 256 * u;
            const int r = idx >> 3;
            const int c4 = (idx & 7) * 4;
            const float4 v = *(const float4*)&A[(size_t)(m0 + r) * D_MODEL + kb + c4];
            const __nv_bfloat16 h0 = __float2bfloat16(v.x);
            const __nv_bfloat16 h1 = __float2bfloat16(v.y);
            const __nv_bfloat16 h2 = __float2bfloat16(v.z);
            const __nv_bfloat16 h3 = __float2bfloat16(v.w);
            const __nv_bfloat16 l0 = __float2bfloat16(v.x - __bfloat162float(h0));
            const __nv_bfloat16 l1 = __float2bfloat16(v.y - __bfloat162float(h1));
            const __nv_bfloat16 l2 = __float2bfloat16(v.z - __bfloat162float(h2));
            const __nv_bfloat16 l3 = __float2bfloat16(v.w - __bfloat162float(h3));
            __nv_bfloat162 H0(h0, h1), H1(h2, h3), L0(l0, l1), L1(l2, l3);
            uint2 uh, ul;
            uh.x = *(uint32_t*)&H0; uh.y = *(uint32_t*)&H1;
            ul.x = *(uint32_t*)&L0; ul.y = *(uint32_t*)&L1;
            const uint32_t so = (uint32_t)(r * (LDR * 2) + c4 * 2);
            *(uint2*)(smx + SOFF_AHI + so) = uh;
            *(uint2*)(smx + SOFF_ALO + so) = ul;
        }
        #pragma unroll
        for (int u = 0; u < 2; u++) {
            const int idx = t + 256 * u;
            const int r = idx >> 2;
            const int q = idx & 3;
            const size_t e = (size_t)(n0 + r) * D_MODEL + kb + q * 8;
            const uint32_t so = (uint32_t)(r * (LDR * 2) + q * 16);
            *(uint4*)(smx + SOFF_BHI + so) = *(const uint4*)&Bhi[e];
            *(uint4*)(smx + SOFF_BLO + so) = *(const uint4*)&Blo[e];
        }
        __syncthreads();

        #pragma unroll
        for (int ks = 0; ks < 2; ks++) {
            const uint32_t kbyte = (uint32_t)(ks * 32);
            uint32_t bh[8], bl[8];
            #pragma unroll
            for (int g = 0; g < 2; g++) {
                const uint32_t nbase = (uint32_t)((warp_n * 32 + g * 16) * (LDR * 2));
                ldsm4(&bh[g * 4], sbase + SOFF_BHI + nbase + kbyte + boff);
                ldsm4(&bl[g * 4], sbase + SOFF_BLO + nbase + kbyte + boff);
            }
            #pragma unroll
            for (int mt = 0; mt < 4; mt++) {
                const uint32_t mbase = (uint32_t)((warp_m * 64 + mt * 16) * (LDR * 2));
                uint32_t ah[4], al[4];
                ldsm4(ah, sbase + SOFF_AHI + mbase + kbyte + aoff);
                ldsm4(al, sbase + SOFF_ALO + mbase + kbyte + aoff);
                #pragma unroll
                for (int nt = 0; nt < 4; nt++) {
                    const int g = nt >> 1, j = (nt & 1) * 2;
                    mma16816(acc[mt][nt], ah, bh[g * 4 + j], bh[g * 4 + j + 1]);
                    mma16816(acc[mt][nt], ah, bl[g * 4 + j], bl[g * 4 + j + 1]);
                    mma16816(acc[mt][nt], al, bh[g * 4 + j], bh[g * 4 + j + 1]);
                }
            }
        }
    }

    #pragma unroll
    for (int mt = 0; mt < 4; mt++) {
        const int row = m0 + warp_m * 64 + mt * 16 + (lane >> 2);
        #pragma unroll
        for (int nt = 0; nt < 4; nt++) {
            const int col = n0 + warp_n * 32 + nt * 8 + (lane & 3) * 2;
            float2 v0 = make_float2(acc[mt][nt][0], acc[mt][nt][1]);
            float2 v1 = make_float2(acc[mt][nt][2], acc[mt][nt][3]);
            *(float2*)&C[(size_t)row * Ntot + col] = v0;
            *(float2*)&C[(size_t)(row + 8) * Ntot + col] = v1;
        }
    }
}

// ===========================================================================
// HMMA flash attention. CTA = 128 queries of one (b,h); 64-key tiles.
// fp16 Q(scaled)/K/V; S and O accum fp32; P reused in registers as A-frag.
// smem rows 72 halves (144B) -> conflict-free ldmatrix.
// ===========================================================================
#define LDA 144             // bytes per smem row (72 halves)
#define ASQ 0
#define ASK (128 * LDA)
#define ASV (ASK + 64 * LDA)
#define ATTN_SMEM (ASV + 64 * LDA)      // 36864 B

__global__ __launch_bounds__(256, 2) void attn_kernel()
{
    __shared__ __align__(16) char sma[ATTN_SMEM];
    const uint32_t sb = smem_u32(sma);

    const int t = threadIdx.x, lane = t & 31, wid = t >> 5;
    const int bh = blockIdx.y;
    const int h = bh & (N_HEADS - 1);
    const int b = bh >> 4;
    const int q0 = blockIdx.x * 128;

    const __half* Bh = g_qkvh + (size_t)b * SEQ * NQKV + h * 192;

    // load Q tile (fp16, pre-scaled)
    #pragma unroll
    for (int u = 0; u < 4; u++) {
        const int idx = t + 256 * u;            // 0..1023 uint4 (8 halves)
        const int r = idx >> 3;
        const int e8 = (idx & 7) * 8;
        *(uint4*)(sma + ASQ + r * LDA + e8 * 2) =
            *(const uint4*)&Bh[(size_t)(q0 + r) * NQKV + e8];
    }

    const uint32_t aoff = (uint32_t)(((lane & 7) + ((lane >> 3) & 1) * 8) * LDA
                                     + ((lane >> 4) & 1) * 16);
    const uint32_t boff = (uint32_t)(((lane & 7) + ((lane >> 4) & 1) * 8) * LDA
                                     + ((lane >> 3) & 1) * 16);
    const uint32_t qbase = sb + ASQ + (uint32_t)(wid * 16) * LDA + aoff;
    const uint32_t kbase = sb + ASK + boff;
    const uint32_t vbase = sb + ASV + aoff;    // trans ldmatrix uses aoff form

    float oacc[8][4];
    #pragma unroll
    for (int q = 0; q < 8; q++)
        #pragma unroll
        for (int v = 0; v < 4; v++) oacc[q][v] = 0.0f;
    float m0_ = -1e30f, m1_ = -1e30f, l0_ = 0.0f, l1_ = 0.0f;

    for (int kt = 0; kt < SEQ; kt += 64) {
        __syncthreads();
        #pragma unroll
        for (int u = 0; u < 2; u++) {
            const int idx = t + 256 * u;        // 0..511
            const int r = idx >> 3;
            const int e8 = (idx & 7) * 8;
            const size_t g = (size_t)(kt + r) * NQKV + e8;
            *(uint4*)(sma + ASK + r * LDA + e8 * 2) = *(const uint4*)&Bh[g + 64];
            *(uint4*)(sma + ASV + r * LDA + e8 * 2) = *(const uint4*)&Bh[g + 128];
        }
        __syncthreads();

        // ---- S = Q K^T (scaled) : warp rows wid*16.., 64 keys ----
        float sacc[8][4];
        #pragma unroll
        for (int q = 0; q < 8; q++)
            #pragma unroll
            for (int v = 0; v < 4; v++) sacc[q][v] = 0.0f;
        #pragma unroll
        for (int ks = 0; ks < 4; ks++) {
            uint32_t a[4];
            ldsm4(a, qbase + ks * 32);
            #pragma unroll
            for (int p = 0; p < 4; p++) {
                uint32_t kb[4];
                ldsm4(kb, kbase + (uint32_t)(p * 16) * LDA + ks * 32);
                mma16816h(sacc[2 * p], a, kb[0], kb[1]);
                mma16816h(sacc[2 * p + 1], a, kb[2], kb[3]);
            }
        }

        // ---- online softmax (rows r0=lane>>2, r1=r0+8) ----
        float mx0 = -1e30f, mx1 = -1e30f;
        #pragma unroll
        for (int nt = 0; nt < 8; nt++) {
            mx0 = fmaxf(mx0, fmaxf(sacc[nt][0], sacc[nt][1]));
            mx1 = fmaxf(mx1, fmaxf(sacc[nt][2], sacc[nt][3]));
        }
        mx0 = fmaxf(mx0, __shfl_xor_sync(0xffffffffu, mx0, 1));
        mx0 = fmaxf(mx0, __shfl_xor_sync(0xffffffffu, mx0, 2));
        mx1 = fmaxf(mx1, __shfl_xor_sync(0xffffffffu, mx1, 1));
        mx1 = fmaxf(mx1, __shfl_xor_sync(0xffffffffu, mx1, 2));
        const float mn0 = fmaxf(m0_, mx0), mn1 = fmaxf(m1_, mx1);
        const float al0 = __expf(m0_ - mn0), al1 = __expf(m1_ - mn1);

        uint32_t ph[8][2];
        float ps0 = 0.0f, ps1 = 0.0f;
        #pragma unroll
        for (int nt = 0; nt < 8; nt++) {
            const float p00 = __expf(sacc[nt][0] - mn0);
            const float p01 = __expf(sacc[nt][1] - mn0);
            const float p10 = __expf(sacc[nt][2] - mn1);
            const float p11 = __expf(sacc[nt][3] - mn1);
            ps0 += p00 + p01; ps1 += p10 + p11;
            __half2 h0 = __floats2half2_rn(p00, p01);
            __half2 h1 = __floats2half2_rn(p10, p11);
            ph[nt][0] = *(uint32_t*)&h0;
            ph[nt][1] = *(uint32_t*)&h1;
        }
        ps0 += __shfl_xor_sync(0xffffffffu, ps0, 1);
        ps0 += __shfl_xor_sync(0xffffffffu, ps0, 2);
        ps1 += __shfl_xor_sync(0xffffffffu, ps1, 1);
        ps1 += __shfl_xor_sync(0xffffffffu, ps1, 2);
        l0_ = l0_ * al0 + ps0; l1_ = l1_ * al1 + ps1;
        m0_ = mn0; m1_ = mn1;
        #pragma unroll
        for (int q = 0; q < 8; q++) {
            oacc[q][0] *= al0; oacc[q][1] *= al0;
            oacc[q][2] *= al1; oacc[q][3] *= al1;
        }

        // ---- O += P V : P fragments straight from registers ----
        #pragma unroll
        for (int kv = 0; kv < 4; kv++) {
            const uint32_t pa[4] = { ph[2 * kv][0], ph[2 * kv][1],
                                     ph[2 * kv + 1][0], ph[2 * kv + 1][1] };
            #pragma unroll
            for (int q = 0; q < 4; q++) {
                uint32_t vb[4];
                ldsm4t(vb, vbase + (uint32_t)(kv * 16) * LDA + q * 32);
                mma16816h(oacc[2 * q], pa, vb[0], vb[1]);
                mma16816h(oacc[2 * q + 1], pa, vb[2], vb[3]);
            }
        }
    }

    // ---- epilogue: normalize, write z (fp32) ----
    const float il0 = 1.0f / l0_, il1 = 1.0f / l1_;
    const size_t grow0 = (size_t)b * SEQ + q0 + wid * 16 + (lane >> 2);
    #pragma unroll
    for (int q = 0; q < 8; q++) {
        const int col = h * HEAD_DIM + q * 8 + (lane & 3) * 2;
        *(float2*)&g_z[grow0 * D_MODEL + col] =
            make_float2(oacc[q][0] * il0, oacc[q][1] * il0);
        *(float2*)&g_z[(grow0 + 8) * D_MODEL + col] =
            make_float2(oacc[q][2] * il1, oacc[q][3] * il1);
    }
}

// ===========================================================================
extern "C" void kernel_launch(void* const* d_in, const int* in_sizes, int n_in,
                              void* d_out, int out_size)
{
    const float* x     = (const float*)d_in[0];  // [4,2048,1024]
    const float* w_qkv = (const float*)d_in[1];  // [16,1024,192]
    const float* w_out = (const float*)d_in[2];  // [1024,1024]
    float* out = (float*)d_out;                  // [8192,1024]

    fmt_wqkv_kernel<<<NQKV, 256>>>(w_qkv);
    fmt_wout_kernel<<<D_MODEL, 256>>>(w_out);

    __nv_bfloat16 *bqh, *bql, *boh, *bol;
    float *qkvp, *zp;
    cudaGetSymbolAddress((void**)&bqh, gBq_hi);
    cudaGetSymbolAddress((void**)&bql, gBq_lo);
    cudaGetSymbolAddress((void**)&boh, gBo_hi);
    cudaGetSymbolAddress((void**)&bol, gBo_lo);
    cudaGetSymbolAddress((void**)&qkvp, g_qkv);
    cudaGetSymbolAddress((void**)&zp, g_z);

    gemm_kernel<<<dim3(NQKV / 128, ROWS / 128), 256>>>(x, bqh, bql, qkvp, NQKV);
    fmt_qkvh_kernel<<<ROWS, 256>>>();
    attn_kernel<<<dim3(SEQ / 128, BATCH * N_HEADS), 256>>>();
    gemm_kernel<<<dim3(D_MODEL / 128, ROWS / 128), 256>>>(zp, boh, bol, out, D_MODEL);
}